// round 16
// baseline (speedup 1.0000x reference)
#include <cuda_runtime.h>
#include <cuda_fp16.h>
#include <math.h>
#include <stdint.h>

#define B 4096
#define D 1024
#define INV_T 20.0f
#define LOG2E 1.4426950408889634f
#define LN2 0.6931471805599453f
#define SHIFT 96.0f

#define TM 128
#define TN 128
#define KC 64                  // K elements per stage (=128B rows of f16)
#define NIT (D / KC)           // 16
#define NSTAGE 3
#define NSPLIT (B / TN)        // 32
#define ROWB 128               // compact rows, SW128 swizzle
#define MAT_BYTES (128 * ROWB)           // 16384
#define STAGE_BYTES (2 * MAT_BYTES)      // 32768
#define DYN_SMEM (NSTAGE * STAGE_BYTES)  // 98304
#define NFIN 16
#define NTHR 512

#define SW128(off) ((off) ^ (((off) >> 3) & 0x70))

// -------- scratch --------
__device__ float g_norm_t[B];
__device__ float g_norm_m[B];
__device__ float g_diag[B];
__device__ float g_psum[NSPLIT][B];
__device__ float g_fin[NFIN];
__device__ int   g_tick = 0;
__device__ __half g_tb[B * D];
__device__ __half g_mb[B * D];

__device__ __forceinline__ uint32_t smem_u32(const void* p) {
    uint32_t a;
    asm("{ .reg .u64 t; cvta.to.shared.u64 t, %1; cvt.u32.u64 %0, t; }" : "=r"(a) : "l"(p));
    return a;
}
__device__ __forceinline__ void cp_async16(uint32_t dst, const void* src) {
    asm volatile("cp.async.cg.shared.global [%0], [%1], 16;\n" :: "r"(dst), "l"(src));
}
__device__ __forceinline__ void ldsm_x4(uint32_t* r, uint32_t addr) {
    asm volatile("ldmatrix.sync.aligned.m8n8.x4.shared.b16 {%0,%1,%2,%3}, [%4];"
                 : "=r"(r[0]), "=r"(r[1]), "=r"(r[2]), "=r"(r[3]) : "r"(addr));
}
__device__ __forceinline__ void mma_f16h(uint32_t* d, const uint32_t* a, const uint32_t* b) {
    asm volatile(
        "mma.sync.aligned.m16n8k16.row.col.f16.f16.f16.f16 "
        "{%0,%1}, {%2,%3,%4,%5}, {%6,%7}, {%0,%1};"
        : "+r"(d[0]), "+r"(d[1])
        : "r"(a[0]), "r"(a[1]), "r"(a[2]), "r"(a[3]), "r"(b[0]), "r"(b[1]));
}
__device__ __forceinline__ uint32_t pack_h2(float x, float y) {
    __half2 v = __floats2half2_rn(x, y);
    return *(uint32_t*)&v;
}

// ==================== Kernel 1: norms + diag + f16 convert ====================
__global__ void __launch_bounds__(128) norms_kernel(const float* __restrict__ t,
                                                    const float* __restrict__ m) {
    int row = blockIdx.x;
    const float* tr = t + (size_t)row * D;
    const float* mr = m + (size_t)row * D;
    int k = threadIdx.x * 8;

    float4 t0 = *(const float4*)&tr[k];
    float4 t1 = *(const float4*)&tr[k + 4];
    float4 m0 = *(const float4*)&mr[k];
    float4 m1 = *(const float4*)&mr[k + 4];

    uint4 tb = make_uint4(pack_h2(t0.x, t0.y), pack_h2(t0.z, t0.w),
                          pack_h2(t1.x, t1.y), pack_h2(t1.z, t1.w));
    uint4 mb = make_uint4(pack_h2(m0.x, m0.y), pack_h2(m0.z, m0.w),
                          pack_h2(m1.x, m1.y), pack_h2(m1.z, m1.w));
    *(uint4*)&g_tb[(size_t)row * D + k] = tb;
    *(uint4*)&g_mb[(size_t)row * D + k] = mb;

    float st = t0.x*t0.x + t0.y*t0.y + t0.z*t0.z + t0.w*t0.w
             + t1.x*t1.x + t1.y*t1.y + t1.z*t1.z + t1.w*t1.w;
    float sm = m0.x*m0.x + m0.y*m0.y + m0.z*m0.z + m0.w*m0.w
             + m1.x*m1.x + m1.y*m1.y + m1.z*m1.z + m1.w*m1.w;
    float sd = t0.x*m0.x + t0.y*m0.y + t0.z*m0.z + t0.w*m0.w
             + t1.x*m1.x + t1.y*m1.y + t1.z*m1.z + t1.w*m1.w;

    #pragma unroll
    for (int off = 16; off > 0; off >>= 1) {
        st += __shfl_xor_sync(0xffffffffu, st, off);
        sm += __shfl_xor_sync(0xffffffffu, sm, off);
        sd += __shfl_xor_sync(0xffffffffu, sd, off);
    }
    __shared__ float sst[4], ssm[4], ssd[4];
    int warp = threadIdx.x >> 5, lane = threadIdx.x & 31;
    if (lane == 0) { sst[warp] = st; ssm[warp] = sm; ssd[warp] = sd; }
    __syncthreads();
    if (threadIdx.x == 0) {
        g_norm_t[row] = sst[0] + sst[1] + sst[2] + sst[3];
        g_norm_m[row] = ssm[0] + ssm[1] + ssm[2] + ssm[3];
        g_diag[row]   = ssd[0] + ssd[1] + ssd[2] + ssd[3];
    }
}

// ==================== Kernel 2: f16 mma GEMM, 512 thr, 3-stage ================
__device__ __forceinline__ void load_stage(uint32_t aBase, uint32_t bBase,
                                           int i0, int j0, int k0, int tid) {
    // stage = 128 rows x 128B (8 chunks of 16B) for A and B; 2 chunks/thread each
    #pragma unroll
    for (int p = 0; p < 2; p++) {
        int c = tid + p * NTHR;
        int r = c >> 3, s = c & 7;
        uint32_t sw = SW128(r * ROWB + s * 16);
        cp_async16(aBase + sw, g_tb + (size_t)(i0 + r) * D + k0 + s * 8);
        cp_async16(bBase + sw, g_mb + (size_t)(j0 + r) * D + k0 + s * 8);
    }
    asm volatile("cp.async.commit_group;\n" ::: "memory");
}

__global__ void __launch_bounds__(NTHR, 2)
gemm_lse() {
    extern __shared__ char dsm[];
    __shared__ float s_nt[TM], s_nm[TN], s_row[TM];

    const int tid = threadIdx.x;
    const int w = tid >> 5, lane = tid & 31;
    const int wm = w & 3, wn = w >> 2;          // 4 M-warps x 4 N-warps, 32x32 tile
    const int g = lane >> 2, tq = lane & 3;
    const int i0 = blockIdx.x * TM;
    const int j0 = blockIdx.y * TN;

    const uint32_t sbase = smem_u32(dsm);

    if (tid < TM) {
        s_row[tid] = 0.0f;
        s_nt[tid] = g_norm_t[i0 + tid];
        s_nm[tid] = g_norm_m[j0 + tid];
    }

    // ldmatrix swizzled per-lane addressing
    const uint32_t xr = (lane & 7) << 4;
    const int rA = (lane & 7) + ((lane >> 3) & 1) * 8;
    const uint32_t rowA = (wm * 32 + rA) * ROWB;            // + mt*16*ROWB, mt<2
    const uint32_t colxA = (uint32_t)((lane >> 4) * 16) ^ xr;
    const int rB = (lane & 7) + ((lane >> 4) & 1) * 8;
    const uint32_t rowBq = (wn * 32 + rB) * ROWB;           // + np*16*ROWB, np<2
    const uint32_t colxB = (uint32_t)(((lane >> 3) & 1) * 16) ^ xr;

    uint32_t acc[2][4][2];                      // f16x2 accumulators (16 regs)
    #pragma unroll
    for (int mt = 0; mt < 2; mt++)
        #pragma unroll
        for (int nt = 0; nt < 4; nt++) { acc[mt][nt][0] = 0u; acc[mt][nt][1] = 0u; }

    // prologue: stages 0,1
    load_stage(sbase, sbase + MAT_BYTES, i0, j0, 0, tid);
    load_stage(sbase + STAGE_BYTES, sbase + STAGE_BYTES + MAT_BYTES, i0, j0, KC, tid);

    for (int it = 0; it < NIT; it++) {
        asm volatile("cp.async.wait_group 1;\n" ::: "memory");
        __syncthreads();

        if (it + 2 < NIT) {
            const uint32_t nb = sbase + ((it + 2) % NSTAGE) * STAGE_BYTES;
            load_stage(nb, nb + MAT_BYTES, i0, j0, (it + 2) * KC, tid);
        } else {
            asm volatile("cp.async.commit_group;\n" ::: "memory");
        }

        const uint32_t st_ = sbase + (it % NSTAGE) * STAGE_BYTES;
        const uint32_t aS = st_ + rowA;
        const uint32_t bS = st_ + MAT_BYTES + rowBq;

        #pragma unroll
        for (int ks = 0; ks < 4; ks++) {              // four k16 steps
            const uint32_t ka  = (uint32_t)(ks * 32) ^ colxA;
            const uint32_t kbx = (uint32_t)(ks * 32) ^ colxB;
            uint32_t af[2][4], bf_[2][4];
            #pragma unroll
            for (int mt = 0; mt < 2; mt++)
                ldsm_x4(af[mt], aS + mt * (16 * ROWB) + ka);
            #pragma unroll
            for (int np = 0; np < 2; np++)
                ldsm_x4(bf_[np], bS + np * (16 * ROWB) + kbx);
            #pragma unroll
            for (int mt = 0; mt < 2; mt++) {
                #pragma unroll
                for (int nt = 0; nt < 4; nt++) {
                    const uint32_t* bp = &bf_[nt >> 1][(nt & 1) * 2];
                    mma_f16h(acc[mt][nt], af[mt], bp);
                }
            }
        }
    }

    // ---- epilogue: logits -> shifted exp2 -> row sums ----
    const float C = -INV_T * LOG2E;
    #pragma unroll
    for (int mt = 0; mt < 2; mt++) {
        #pragma unroll
        for (int rh = 0; rh < 2; rh++) {
            const int row = wm * 32 + mt * 16 + g + rh * 8;
            const int gi = i0 + row;
            const float nt_ = s_nt[row];
            float rs = 0.0f;
            #pragma unroll
            for (int nt = 0; nt < 4; nt++) {
                const __half2 hv = *(const __half2*)&acc[mt][nt][rh];
                const float av[2] = { __low2float(hv), __high2float(hv) };
                #pragma unroll
                for (int cc = 0; cc < 2; cc++) {
                    const int col = wn * 32 + nt * 8 + tq * 2 + cc;
                    float dsq = fmaxf(fmaf(-2.0f, av[cc], nt_ + s_nm[col]), 1e-20f);
                    float dd; asm("sqrt.approx.f32 %0, %1;" : "=f"(dd) : "f"(dsq));
                    float x = fmaf(dd, C, SHIFT);
                    float e; asm("ex2.approx.f32 %0, %1;" : "=f"(e) : "f"(x));
                    rs += ((j0 + col) == gi) ? 0.0f : e;
                }
            }
            rs += __shfl_xor_sync(0xffffffffu, rs, 1);
            rs += __shfl_xor_sync(0xffffffffu, rs, 2);
            if (tq == 0) atomicAdd(&s_row[row], rs);
        }
    }
    __syncthreads();
    if (tid < TM) g_psum[blockIdx.y][i0 + tid] = s_row[tid];
}

// ==================== Kernel 3: finalize (ticketed single kernel) ====
__global__ void __launch_bounds__(256) finalize_kernel(float* __restrict__ out) {
    __shared__ float red[256];
    __shared__ int s_last;
    const int i = blockIdx.x * 256 + threadIdx.x;   // one row per thread
    float S = 0.0f;
    #pragma unroll
    for (int s = 0; s < NSPLIT; s++) S += g_psum[s][i];
    float lse = logf(S) - SHIFT * LN2;
    float dsq = g_norm_t[i] + g_norm_m[i] - 2.0f * g_diag[i];
    float dii = sqrtf(fmaxf(dsq, 0.0f));
    red[threadIdx.x] = lse + dii * INV_T;
    __syncthreads();
    #pragma unroll
    for (int off = 128; off > 0; off >>= 1) {
        if (threadIdx.x < off) red[threadIdx.x] += red[threadIdx.x + off];
        __syncthreads();
    }
    if (threadIdx.x == 0) {
        g_fin[blockIdx.x] = red[0];
        __threadfence();
        int t = atomicAdd(&g_tick, 1);
        s_last = (t == NFIN - 1);
    }
    __syncthreads();
    if (s_last && threadIdx.x < 32) {
        float v = (threadIdx.x < NFIN) ? g_fin[threadIdx.x] : 0.0f;
        #pragma unroll
        for (int off = 16; off > 0; off >>= 1)
            v += __shfl_xor_sync(0xffffffffu, v, off);
        if (threadIdx.x == 0) { out[0] = v / (float)B; g_tick = 0; }
    }
}

// ==================== launch ====================
extern "C" void kernel_launch(void* const* d_in, const int* in_sizes, int n_in,
                              void* d_out, int out_size) {
    const float* t = (const float*)d_in[0];
    const float* m = (const float*)d_in[1];
    (void)in_sizes; (void)n_in; (void)out_size;

    cudaFuncSetAttribute(gemm_lse, cudaFuncAttributeMaxDynamicSharedMemorySize, DYN_SMEM);

    norms_kernel<<<B, 128>>>(t, m);
    gemm_lse<<<dim3(B / TM, B / TN), NTHR, DYN_SMEM>>>();
    finalize_kernel<<<NFIN, 256>>>((float*)d_out);
}

// round 17
// speedup vs baseline: 1.1319x; 1.1319x over previous
#include <cuda_runtime.h>
#include <cuda_fp16.h>
#include <math.h>
#include <stdint.h>

#define B 4096
#define D 1024
#define INV_T 20.0f
#define LOG2E 1.4426950408889634f
#define LN2 0.6931471805599453f
#define SHIFT 96.0f

#define TM 128
#define TN 128
#define KC 64                  // K elements per stage (=128B rows of f16)
#define NIT (D / KC)           // 16
#define NSPLIT (B / TN)        // 32
#define ROWB 128               // compact rows, SW128 swizzle
#define MAT_BYTES (128 * ROWB)           // 16384
#define STAGE_BYTES (2 * MAT_BYTES)      // 32768
#define DYN_SMEM (2 * STAGE_BYTES)       // 65536
#define NFIN 16

#define SW128(off) ((off) ^ (((off) >> 3) & 0x70))

// -------- scratch --------
__device__ float g_norm_t[B];
__device__ float g_norm_m[B];
__device__ float g_diag[B];
__device__ float g_psum[NSPLIT][B];
__device__ float g_fin[NFIN];
__device__ int   g_tick = 0;
__device__ __half g_tb[B * D];
__device__ __half g_mb[B * D];

__device__ __forceinline__ uint32_t smem_u32(const void* p) {
    uint32_t a;
    asm("{ .reg .u64 t; cvta.to.shared.u64 t, %1; cvt.u32.u64 %0, t; }" : "=r"(a) : "l"(p));
    return a;
}
__device__ __forceinline__ void cp_async16(uint32_t dst, const void* src) {
    asm volatile("cp.async.cg.shared.global [%0], [%1], 16;\n" :: "r"(dst), "l"(src));
}
__device__ __forceinline__ void ldsm_x4(uint32_t* r, uint32_t addr) {
    asm volatile("ldmatrix.sync.aligned.m8n8.x4.shared.b16 {%0,%1,%2,%3}, [%4];"
                 : "=r"(r[0]), "=r"(r[1]), "=r"(r[2]), "=r"(r[3]) : "r"(addr));
}
__device__ __forceinline__ void mma_f16h(uint32_t* d, const uint32_t* a, const uint32_t* b) {
    asm volatile(
        "mma.sync.aligned.m16n8k16.row.col.f16.f16.f16.f16 "
        "{%0,%1}, {%2,%3,%4,%5}, {%6,%7}, {%0,%1};"
        : "+r"(d[0]), "+r"(d[1])
        : "r"(a[0]), "r"(a[1]), "r"(a[2]), "r"(a[3]), "r"(b[0]), "r"(b[1]));
}
__device__ __forceinline__ uint32_t pack_h2(float x, float y) {
    __half2 v = __floats2half2_rn(x, y);
    return *(uint32_t*)&v;
}

// ==================== Kernel 1: norms + diag + f16 convert ====================
__global__ void __launch_bounds__(128) norms_kernel(const float* __restrict__ t,
                                                    const float* __restrict__ m) {
    int row = blockIdx.x;
    const float* tr = t + (size_t)row * D;
    const float* mr = m + (size_t)row * D;
    int k = threadIdx.x * 8;

    float4 t0 = *(const float4*)&tr[k];
    float4 t1 = *(const float4*)&tr[k + 4];
    float4 m0 = *(const float4*)&mr[k];
    float4 m1 = *(const float4*)&mr[k + 4];

    uint4 tb = make_uint4(pack_h2(t0.x, t0.y), pack_h2(t0.z, t0.w),
                          pack_h2(t1.x, t1.y), pack_h2(t1.z, t1.w));
    uint4 mb = make_uint4(pack_h2(m0.x, m0.y), pack_h2(m0.z, m0.w),
                          pack_h2(m1.x, m1.y), pack_h2(m1.z, m1.w));
    *(uint4*)&g_tb[(size_t)row * D + k] = tb;
    *(uint4*)&g_mb[(size_t)row * D + k] = mb;

    float st = t0.x*t0.x + t0.y*t0.y + t0.z*t0.z + t0.w*t0.w
             + t1.x*t1.x + t1.y*t1.y + t1.z*t1.z + t1.w*t1.w;
    float sm = m0.x*m0.x + m0.y*m0.y + m0.z*m0.z + m0.w*m0.w
             + m1.x*m1.x + m1.y*m1.y + m1.z*m1.z + m1.w*m1.w;
    float sd = t0.x*m0.x + t0.y*m0.y + t0.z*m0.z + t0.w*m0.w
             + t1.x*m1.x + t1.y*m1.y + t1.z*m1.z + t1.w*m1.w;

    #pragma unroll
    for (int off = 16; off > 0; off >>= 1) {
        st += __shfl_xor_sync(0xffffffffu, st, off);
        sm += __shfl_xor_sync(0xffffffffu, sm, off);
        sd += __shfl_xor_sync(0xffffffffu, sd, off);
    }
    __shared__ float sst[4], ssm[4], ssd[4];
    int warp = threadIdx.x >> 5, lane = threadIdx.x & 31;
    if (lane == 0) { sst[warp] = st; ssm[warp] = sm; ssd[warp] = sd; }
    __syncthreads();
    if (threadIdx.x == 0) {
        g_norm_t[row] = sst[0] + sst[1] + sst[2] + sst[3];
        g_norm_m[row] = ssm[0] + ssm[1] + ssm[2] + ssm[3];
        g_diag[row]   = ssd[0] + ssd[1] + ssd[2] + ssd[3];
    }
}

// ==================== Kernel 2: f16 mma GEMM, SW128, 3 CTA/SM, 1 barrier/iter ==
__device__ __forceinline__ void load_stage(uint32_t aBase, uint32_t bBase,
                                           int i0, int j0, int k0, int tid) {
    #pragma unroll
    for (int p = 0; p < 4; p++) {
        int c = tid + p * 256;
        int r = c >> 3, s = c & 7;
        uint32_t sw = SW128(r * ROWB + s * 16);
        cp_async16(aBase + sw, g_tb + (size_t)(i0 + r) * D + k0 + s * 8);
        cp_async16(bBase + sw, g_mb + (size_t)(j0 + r) * D + k0 + s * 8);
    }
    asm volatile("cp.async.commit_group;\n" ::: "memory");
}

__global__ void __launch_bounds__(256, 3)
gemm_lse() {
    extern __shared__ char dsm[];
    __shared__ float s_nt[TM], s_nm[TN], s_row[TM];

    const int tid = threadIdx.x;
    const int w = tid >> 5, lane = tid & 31;
    const int wm = w & 1, wn = w >> 1;          // 2 M-warps x 4 N-warps, 64x32 tile
    const int g = lane >> 2, tq = lane & 3;
    const int i0 = blockIdx.x * TM;
    const int j0 = blockIdx.y * TN;

    const uint32_t sbase = smem_u32(dsm);

    if (tid < TM) {
        s_row[tid] = 0.0f;
        s_nt[tid] = g_norm_t[i0 + tid];
        s_nm[tid] = g_norm_m[j0 + tid];
    }

    // ldmatrix swizzled per-lane addressing
    const uint32_t xr = (lane & 7) << 4;
    const int rA = (lane & 7) + ((lane >> 3) & 1) * 8;
    const uint32_t rowA = (wm * 64 + rA) * ROWB;            // + mt*16*ROWB
    const uint32_t colxA = (uint32_t)((lane >> 4) * 16) ^ xr;
    const int rB = (lane & 7) + ((lane >> 4) & 1) * 8;
    const uint32_t rowBq = (wn * 32 + rB) * ROWB;           // + np*16*ROWB
    const uint32_t colxB = (uint32_t)(((lane >> 3) & 1) * 16) ^ xr;

    uint32_t acc[4][4][2];                      // f16x2 accumulators
    #pragma unroll
    for (int mt = 0; mt < 4; mt++)
        #pragma unroll
        for (int nt = 0; nt < 4; nt++) { acc[mt][nt][0] = 0u; acc[mt][nt][1] = 0u; }

    // prologue: stage 0
    load_stage(sbase, sbase + MAT_BYTES, i0, j0, 0, tid);

    for (int it = 0; it < NIT; it++) {
        asm volatile("cp.async.wait_group 0;\n" ::: "memory");
        __syncthreads();
        // distance-1 prefetch into the buffer NOT read this iteration;
        // the barrier above fenced its previous readers (iteration it-1).
        if (it + 1 < NIT) {
            const uint32_t nb = sbase + ((it + 1) & 1) * STAGE_BYTES;
            load_stage(nb, nb + MAT_BYTES, i0, j0, (it + 1) * KC, tid);
        }

        const uint32_t st_ = sbase + (it & 1) * STAGE_BYTES;
        const uint32_t aS = st_ + rowA;
        const uint32_t bS = st_ + MAT_BYTES + rowBq;

        #pragma unroll
        for (int ks = 0; ks < 4; ks++) {              // four k16 steps
            const uint32_t ka  = (uint32_t)(ks * 32) ^ colxA;
            const uint32_t kbx = (uint32_t)(ks * 32) ^ colxB;
            uint32_t af[4][4], bf_[2][4];
            #pragma unroll
            for (int mt = 0; mt < 4; mt++)
                ldsm_x4(af[mt], aS + mt * (16 * ROWB) + ka);
            #pragma unroll
            for (int np = 0; np < 2; np++)
                ldsm_x4(bf_[np], bS + np * (16 * ROWB) + kbx);
            #pragma unroll
            for (int mt = 0; mt < 4; mt++) {
                #pragma unroll
                for (int nt = 0; nt < 4; nt++) {
                    const uint32_t* bp = &bf_[nt >> 1][(nt & 1) * 2];
                    mma_f16h(acc[mt][nt], af[mt], bp);
                }
            }
        }
    }

    // ---- epilogue: logits -> shifted exp2 -> row sums ----
    const float C = -INV_T * LOG2E;
    #pragma unroll
    for (int mt = 0; mt < 4; mt++) {
        #pragma unroll
        for (int rh = 0; rh < 2; rh++) {
            const int row = wm * 64 + mt * 16 + g + rh * 8;
            const int gi = i0 + row;
            const float nt_ = s_nt[row];
            float rs = 0.0f;
            #pragma unroll
            for (int nt = 0; nt < 4; nt++) {
                const __half2 hv = *(const __half2*)&acc[mt][nt][rh];
                const float av[2] = { __low2float(hv), __high2float(hv) };
                #pragma unroll
                for (int cc = 0; cc < 2; cc++) {
                    const int col = wn * 32 + nt * 8 + tq * 2 + cc;
                    float dsq = fmaxf(fmaf(-2.0f, av[cc], nt_ + s_nm[col]), 1e-20f);
                    float dd; asm("sqrt.approx.f32 %0, %1;" : "=f"(dd) : "f"(dsq));
                    float x = fmaf(dd, C, SHIFT);
                    float e; asm("ex2.approx.f32 %0, %1;" : "=f"(e) : "f"(x));
                    rs += ((j0 + col) == gi) ? 0.0f : e;
                }
            }
            rs += __shfl_xor_sync(0xffffffffu, rs, 1);
            rs += __shfl_xor_sync(0xffffffffu, rs, 2);
            if (tq == 0) atomicAdd(&s_row[row], rs);
        }
    }
    __syncthreads();
    if (tid < TM) g_psum[blockIdx.y][i0 + tid] = s_row[tid];
}

// ==================== Kernel 3: finalize (ticketed single kernel) ====
__global__ void __launch_bounds__(256) finalize_kernel(float* __restrict__ out) {
    __shared__ float red[256];
    __shared__ int s_last;
    const int i = blockIdx.x * 256 + threadIdx.x;   // one row per thread
    float S = 0.0f;
    #pragma unroll
    for (int s = 0; s < NSPLIT; s++) S += g_psum[s][i];
    float lse = logf(S) - SHIFT * LN2;
    float dsq = g_norm_t[i] + g_norm_m[i] - 2.0f * g_diag[i];
    float dii = sqrtf(fmaxf(dsq, 0.0f));
    red[threadIdx.x] = lse + dii * INV_T;
    __syncthreads();
    #pragma unroll
    for (int off = 128; off > 0; off >>= 1) {
        if (threadIdx.x < off) red[threadIdx.x] += red[threadIdx.x + off];
        __syncthreads();
    }
    if (threadIdx.x == 0) {
        g_fin[blockIdx.x] = red[0];
        __threadfence();
        int t = atomicAdd(&g_tick, 1);
        s_last = (t == NFIN - 1);
    }
    __syncthreads();
    if (s_last && threadIdx.x < 32) {
        float v = (threadIdx.x < NFIN) ? g_fin[threadIdx.x] : 0.0f;
        #pragma unroll
        for (int off = 16; off > 0; off >>= 1)
            v += __shfl_xor_sync(0xffffffffu, v, off);
        if (threadIdx.x == 0) { out[0] = v / (float)B; g_tick = 0; }
    }
}

// ==================== launch ====================
extern "C" void kernel_launch(void* const* d_in, const int* in_sizes, int n_in,
                              void* d_out, int out_size) {
    const float* t = (const float*)d_in[0];
    const float* m = (const float*)d_in[1];
    (void)in_sizes; (void)n_in; (void)out_size;

    cudaFuncSetAttribute(gemm_lse, cudaFuncAttributeMaxDynamicSharedMemorySize, DYN_SMEM);

    norms_kernel<<<B, 128>>>(t, m);
    gemm_lse<<<dim3(B / TM, B / TN), 256, DYN_SMEM>>>();
    finalize_kernel<<<NFIN, 256>>>((float*)d_out);
}